// round 8
// baseline (speedup 1.0000x reference)
#include <cuda_runtime.h>
#include <cuda_fp16.h>
#include <cuda_bf16.h>
#include <cstdint>

#define NC  100000
#define NT  100000
#define NNZ 640000
#define D   128
#define CAP 32           // bucket capacity per row (Poisson mean 6.4)

#define PREP_BLOCKS 1036                 // ~1 full wave
#define PREP_T      256
#define BKT_BLOCKS  (PREP_BLOCKS / 4)    // 259: bucket role (L2-atomic bound)
#define CNV_BLOCKS  (PREP_BLOCKS - BKT_BLOCKS)  // 777: convert role (DRAM bound)
#define BKT_THREADS (BKT_BLOCKS * PREP_T)
#define CNV_THREADS (CNV_BLOCKS * PREP_T)
#define CONV_UNITS  (NT * D / 8)         // 1.6M uint4 units (8 halves each)

// ---- device-global scratch (no allocation allowed) ----
// g_meta[0] = overflow count; g_meta[1..NC] = per-row nnz counts.
__device__ int   g_meta[NC + 1];
__device__ int   g_bucket[NC * CAP];   // col indices bucketed by row (12.8 MB)
__device__ int2  g_ovf[NNZ];           // overflow (row,col) pairs (worst case)
__device__ uint4 g_half[NT * D / 8];   // fp16 copy of mat (25.6 MB)

// Phase 1: role-specialized. 1/4 of blocks bucket the nonzeros (bound by the
// chip-wide L2 atomic/wavefront pipe — extra SMs don't help, R3 vs R4), 3/4
// stream-convert mat fp32->fp16 (DRAM bound). Roles overlap across SMs.
__global__ __launch_bounds__(PREP_T) void prep_kernel(
    const int*    __restrict__ row,
    const int*    __restrict__ col,
    const float4* __restrict__ matf4) {
    const int q    = blockIdx.x >> 2;
    const int rsel = blockIdx.x & 3;

    if (rsel == 0) {
        // ---- bucket role (259 blocks) ----
        int* cnt = g_meta + 1;
        const int tid = q * PREP_T + threadIdx.x;
        #pragma unroll 4
        for (int i = tid; i < NNZ; i += BKT_THREADS) {
            int r = __ldg(row + i);
            int c = __ldg(col + i);
            int slot = atomicAdd(&cnt[r], 1);
            if (slot < CAP) {
                g_bucket[r * CAP + slot] = c;
            } else {
                int p = atomicAdd(&g_meta[0], 1);
                g_ovf[p] = make_int2(r, c);
            }
        }
    } else {
        // ---- convert role (777 blocks): coalesced streaming ----
        const int cid = 3 * q + rsel - 1;           // 0 .. CNV_BLOCKS-1
        const int tid = cid * PREP_T + threadIdx.x;
        for (int p = tid; p < CONV_UNITS; p += CNV_THREADS) {
            float4 a = __ldg(matf4 + 2 * p);
            float4 b = __ldg(matf4 + 2 * p + 1);
            __half2 h0 = __float22half2_rn(make_float2(a.x, a.y));
            __half2 h1 = __float22half2_rn(make_float2(a.z, a.w));
            __half2 h2 = __float22half2_rn(make_float2(b.x, b.y));
            __half2 h3 = __float22half2_rn(make_float2(b.z, b.w));
            uint4 u;
            u.x = *reinterpret_cast<unsigned*>(&h0);
            u.y = *reinterpret_cast<unsigned*>(&h1);
            u.z = *reinterpret_cast<unsigned*>(&h2);
            u.w = *reinterpret_cast<unsigned*>(&h3);
            g_half[p] = u;
        }
    }
}

// Phase 2: TWO rows per warp (doubled per-warp MLP). fp16 row = 256 B =
// 32 lanes x uint2. Per row: one 128B bucket-line load + predicated batch of
// 8 independent row loads; both rows' loads interleave in flight. Rows with
// raw n > CAP scan the (expected-empty) overflow list inline — no separate
// overflow kernel, no atomics anywhere in phase 2.
__global__ __launch_bounds__(256) void gather_sum_kernel(
    float4* __restrict__ out) {
    int gw   = (blockIdx.x * blockDim.x + threadIdx.x) >> 5;
    int lane = threadIdx.x & 31;
    int r0 = gw * 2;
    int r1 = r0 + 1;
    if (r0 >= NC) return;

    const int*   cnt      = g_meta + 1;
    const uint2* halfrows = reinterpret_cast<const uint2*>(g_half);

    // Four independent loads issued up front.
    int cj0 = __ldg(g_bucket + r0 * CAP + lane);
    int cj1 = __ldg(g_bucket + r1 * CAP + lane);
    int nr0 = __ldg(cnt + r0);
    int nr1 = __ldg(cnt + r1);
    int n0 = nr0 > CAP ? CAP : nr0;
    int n1 = nr1 > CAP ? CAP : nr1;

    // Predicated load batches — 16 independent LDGs in flight.
    uint2 v0[8], v1[8];
    #pragma unroll
    for (int j = 0; j < 8; ++j) {
        int c = __shfl_sync(0xffffffffu, cj0, j);
        if (j < n0) v0[j] = __ldg(halfrows + (size_t)c * 32 + lane);
    }
    #pragma unroll
    for (int j = 0; j < 8; ++j) {
        int c = __shfl_sync(0xffffffffu, cj1, j);
        if (j < n1) v1[j] = __ldg(halfrows + (size_t)c * 32 + lane);
    }

    float a0x = 0.f, a0y = 0.f, a0z = 0.f, a0w = 0.f;
    float a1x = 0.f, a1y = 0.f, a1z = 0.f, a1w = 0.f;
    #pragma unroll
    for (int j = 0; j < 8; ++j) {
        if (j < n0) {
            float2 f0 = __half22float2(*reinterpret_cast<__half2*>(&v0[j].x));
            float2 f1 = __half22float2(*reinterpret_cast<__half2*>(&v0[j].y));
            a0x += f0.x; a0y += f0.y; a0z += f1.x; a0w += f1.y;
        }
        if (j < n1) {
            float2 f0 = __half22float2(*reinterpret_cast<__half2*>(&v1[j].x));
            float2 f1 = __half22float2(*reinterpret_cast<__half2*>(&v1[j].y));
            a1x += f0.x; a1y += f0.y; a1z += f1.x; a1w += f1.y;
        }
    }
    // Tails: n in (8, 32] (~20% of rows).
    for (int j = 8; j < n0; ++j) {
        int c = __shfl_sync(0xffffffffu, cj0, j);
        uint2 h = __ldg(halfrows + (size_t)c * 32 + lane);
        float2 f0 = __half22float2(*reinterpret_cast<__half2*>(&h.x));
        float2 f1 = __half22float2(*reinterpret_cast<__half2*>(&h.y));
        a0x += f0.x; a0y += f0.y; a0z += f1.x; a0w += f1.y;
    }
    for (int j = 8; j < n1; ++j) {
        int c = __shfl_sync(0xffffffffu, cj1, j);
        uint2 h = __ldg(halfrows + (size_t)c * 32 + lane);
        float2 f0 = __half22float2(*reinterpret_cast<__half2*>(&h.x));
        float2 f1 = __half22float2(*reinterpret_cast<__half2*>(&h.y));
        a1x += f0.x; a1y += f0.y; a1z += f1.x; a1w += f1.y;
    }

    // Inline overflow handling (expected: никогда — ovf list empty).
    if (nr0 > CAP || nr1 > CAP) {
        int ovfn = __ldg(&g_meta[0]);
        for (int i = 0; i < ovfn; ++i) {
            int2 e = __ldg(g_ovf + i);
            if (e.x == r0 || e.x == r1) {
                uint2 h = __ldg(halfrows + (size_t)e.y * 32 + lane);
                float2 f0 = __half22float2(*reinterpret_cast<__half2*>(&h.x));
                float2 f1 = __half22float2(*reinterpret_cast<__half2*>(&h.y));
                if (e.x == r0) { a0x += f0.x; a0y += f0.y; a0z += f1.x; a0w += f1.y; }
                else           { a1x += f0.x; a1y += f0.y; a1z += f1.x; a1w += f1.y; }
            }
        }
    }

    out[(size_t)r0 * 32 + lane] = make_float4(a0x, a0y, a0z, a0w);
    out[(size_t)r1 * 32 + lane] = make_float4(a1x, a1y, a1z, a1w);
}

extern "C" void kernel_launch(void* const* d_in, const int* in_sizes, int n_in,
                              void* d_out, int out_size) {
    const float4* mat = (const float4*)d_in[0];
    const int*    row = (const int*)d_in[1];
    const int*    col = (const int*)d_in[2];
    float4*       out = (float4*)d_out;

    void* meta_ptr = nullptr;
    cudaGetSymbolAddress(&meta_ptr, g_meta);
    cudaMemsetAsync(meta_ptr, 0, (size_t)(NC + 1) * sizeof(int));

    prep_kernel<<<PREP_BLOCKS, PREP_T>>>(row, col, mat);

    // 50000 warps (2 rows each) = 1.6M threads / 256 = 6250 blocks.
    gather_sum_kernel<<<6250, 256>>>(out);
}

// round 9
// speedup vs baseline: 1.1706x; 1.1706x over previous
#include <cuda_runtime.h>
#include <cuda_fp16.h>
#include <cuda_bf16.h>
#include <cstdint>

#define NC  100000
#define NT  100000
#define NNZ 640000
#define D   128
#define CAP 32           // bucket capacity per row (Poisson mean 6.4)

#define PREP_PAIRS  518                     // grid = 1036 blocks (~1 wave)
#define PREP_T      256
#define PREP_HALF   (PREP_PAIRS * PREP_T)   // threads per role
#define CONV_UNITS  (NT * D / 8)            // 1.6M uint4 units (8 halves each)

// ---- device-global scratch (no allocation allowed) ----
// g_meta[0] = overflow count; g_meta[1..NC] = per-row nnz counts.
__device__ int   g_meta[NC + 1];
__device__ int   g_bucket[NC * CAP];   // col indices bucketed by row (12.8 MB)
__device__ int2  g_ovf[NNZ];           // overflow (row,col) pairs (worst case)
__device__ uint4 g_half[NT * D / 8];   // fp16 copy of mat (25.6 MB)

__device__ __forceinline__ __half2 u2h(unsigned u) {
    return *reinterpret_cast<__half2*>(&u);
}

// Phase 1: role-specialized 1:1 (R7's measured-best split). Even blocks
// stream-convert mat fp32->fp16 (DRAM-bound); odd blocks bucket nonzeros
// (L2-atomic bound). Roles overlap across SMs.
__global__ __launch_bounds__(PREP_T) void prep_kernel(
    const int*    __restrict__ row,
    const int*    __restrict__ col,
    const float4* __restrict__ matf4) {
    const int pair = blockIdx.x >> 1;
    const int tid  = pair * PREP_T + threadIdx.x;

    if ((blockIdx.x & 1) == 0) {
        for (int p = tid; p < CONV_UNITS; p += PREP_HALF) {
            float4 a = __ldg(matf4 + 2 * p);
            float4 b = __ldg(matf4 + 2 * p + 1);
            __half2 h0 = __float22half2_rn(make_float2(a.x, a.y));
            __half2 h1 = __float22half2_rn(make_float2(a.z, a.w));
            __half2 h2 = __float22half2_rn(make_float2(b.x, b.y));
            __half2 h3 = __float22half2_rn(make_float2(b.z, b.w));
            uint4 u;
            u.x = *reinterpret_cast<unsigned*>(&h0);
            u.y = *reinterpret_cast<unsigned*>(&h1);
            u.z = *reinterpret_cast<unsigned*>(&h2);
            u.w = *reinterpret_cast<unsigned*>(&h3);
            g_half[p] = u;
        }
    } else {
        int* cnt = g_meta + 1;
        for (int i = tid; i < NNZ; i += PREP_HALF) {
            int r = __ldg(row + i);
            int c = __ldg(col + i);
            int slot = atomicAdd(&cnt[r], 1);
            if (slot < CAP) {
                g_bucket[r * CAP + slot] = c;
            } else {
                int p = atomicAdd(&g_meta[0], 1);
                g_ovf[p] = make_int2(r, c);
            }
        }
    }
}

// Phase 2: one warp per row, minimal instruction count.
// - 8 predicated loads with ZERO-FILL (no accumulate-side predication).
// - depth-2 fp16 HADD2 tree over the 8 slots (adding packed zeros is exact),
//   converting to fp32 only once per group of 4: 28 fixed math instr/row
//   instead of ~100+ predicated cvt/add.
// - tail (n>8, ~20% of rows) accumulates in fp32 directly.
__global__ __launch_bounds__(256) void gather_sum_kernel(
    float4* __restrict__ out) {
    int r    = (blockIdx.x * blockDim.x + threadIdx.x) >> 5;
    int lane = threadIdx.x & 31;
    if (r >= NC) return;

    const int*   cnt      = g_meta + 1;
    const uint2* halfrows = reinterpret_cast<const uint2*>(g_half);

    int cj = __ldg(g_bucket + r * CAP + lane);
    int nr = __ldg(cnt + r);
    int n  = nr > CAP ? CAP : nr;

    uint2 v[8];
    #pragma unroll
    for (int j = 0; j < 8; ++j) {
        int c = __shfl_sync(0xffffffffu, cj, j);
        uint2 t = make_uint2(0u, 0u);
        if (j < n) t = __ldg(halfrows + (size_t)c * 32 + lane);
        v[j] = t;
    }

    float ax = 0.f, ay = 0.f, az = 0.f, aw = 0.f;
    #pragma unroll
    for (int g = 0; g < 2; ++g) {
        __half2 s0 = __hadd2(u2h(v[4*g+0].x), u2h(v[4*g+1].x));
        __half2 s1 = __hadd2(u2h(v[4*g+2].x), u2h(v[4*g+3].x));
        __half2 p  = __hadd2(s0, s1);
        __half2 q0 = __hadd2(u2h(v[4*g+0].y), u2h(v[4*g+1].y));
        __half2 q1 = __hadd2(u2h(v[4*g+2].y), u2h(v[4*g+3].y));
        __half2 q  = __hadd2(q0, q1);
        float2 fp = __half22float2(p);
        float2 fq = __half22float2(q);
        ax += fp.x; ay += fp.y; az += fq.x; aw += fq.y;
    }

    // Tail: n in (8, 32], fp32 accumulation.
    for (int j = 8; j < n; ++j) {
        int c = __shfl_sync(0xffffffffu, cj, j);
        uint2 h = __ldg(halfrows + (size_t)c * 32 + lane);
        float2 f0 = __half22float2(u2h(h.x));
        float2 f1 = __half22float2(u2h(h.y));
        ax += f0.x; ay += f0.y; az += f1.x; aw += f1.y;
    }

    // Inline overflow handling (expected count 0; list scanned only by rows
    // whose raw count exceeded CAP).
    if (nr > CAP) {
        int ovfn = __ldg(&g_meta[0]);
        for (int i = 0; i < ovfn; ++i) {
            int2 e = __ldg(g_ovf + i);
            if (e.x == r) {
                uint2 h = __ldg(halfrows + (size_t)e.y * 32 + lane);
                float2 f0 = __half22float2(u2h(h.x));
                float2 f1 = __half22float2(u2h(h.y));
                ax += f0.x; ay += f0.y; az += f1.x; aw += f1.y;
            }
        }
    }

    out[(size_t)r * 32 + lane] = make_float4(ax, ay, az, aw);
}

extern "C" void kernel_launch(void* const* d_in, const int* in_sizes, int n_in,
                              void* d_out, int out_size) {
    const float4* mat = (const float4*)d_in[0];
    const int*    row = (const int*)d_in[1];
    const int*    col = (const int*)d_in[2];
    float4*       out = (float4*)d_out;

    void* meta_ptr = nullptr;
    cudaGetSymbolAddress(&meta_ptr, g_meta);
    cudaMemsetAsync(meta_ptr, 0, (size_t)(NC + 1) * sizeof(int));

    prep_kernel<<<PREP_PAIRS * 2, PREP_T>>>(row, col, mat);

    // 100000 warps = 3.2M threads / 256 = 12500 blocks.
    gather_sum_kernel<<<12500, 256>>>(out);
}

// round 10
// speedup vs baseline: 1.1831x; 1.0106x over previous
#include <cuda_runtime.h>
#include <cuda_fp16.h>
#include <cuda_bf16.h>
#include <cstdint>

#define NC  100000
#define NT  100000
#define NNZ 640000
#define D   128
#define CAP 16           // bucket capacity (P(n>16)~3e-4 -> inline overflow)

#define PREP_PAIRS  518                     // grid = 1036 blocks (~1 wave)
#define PREP_T      256
#define PREP_HALF   (PREP_PAIRS * PREP_T)   // threads per role
#define CONV_UNITS  (NT * D / 8)            // 1.6M uint4 units (8 halves each)

// ---- device-global scratch (no allocation allowed) ----
// g_meta[0] = overflow count; g_meta[1..NC] = per-row nnz counts.
__device__ int   g_meta[NC + 1];
__device__ int   g_bucket[NC * CAP];   // col indices bucketed by row (6.4 MB)
__device__ int2  g_ovf[NNZ];           // overflow (row,col) pairs (worst case)
__device__ uint4 g_half[NT * D / 8];   // fp16 copy of mat (25.6 MB)

__device__ __forceinline__ __half2 u2h(unsigned u) {
    return *reinterpret_cast<__half2*>(&u);
}

// Phase 1: role-specialized 1:1 (measured best). Even blocks stream-convert
// mat fp32->fp16 (DRAM-bound); odd blocks bucket nonzeros (L2-atomic bound).
__global__ __launch_bounds__(PREP_T) void prep_kernel(
    const int*    __restrict__ row,
    const int*    __restrict__ col,
    const float4* __restrict__ matf4) {
    const int pair = blockIdx.x >> 1;
    const int tid  = pair * PREP_T + threadIdx.x;

    if ((blockIdx.x & 1) == 0) {
        for (int p = tid; p < CONV_UNITS; p += PREP_HALF) {
            float4 a = __ldg(matf4 + 2 * p);
            float4 b = __ldg(matf4 + 2 * p + 1);
            __half2 h0 = __float22half2_rn(make_float2(a.x, a.y));
            __half2 h1 = __float22half2_rn(make_float2(a.z, a.w));
            __half2 h2 = __float22half2_rn(make_float2(b.x, b.y));
            __half2 h3 = __float22half2_rn(make_float2(b.z, b.w));
            uint4 u;
            u.x = *reinterpret_cast<unsigned*>(&h0);
            u.y = *reinterpret_cast<unsigned*>(&h1);
            u.z = *reinterpret_cast<unsigned*>(&h2);
            u.w = *reinterpret_cast<unsigned*>(&h3);
            g_half[p] = u;
        }
    } else {
        int* cnt = g_meta + 1;
        for (int i = tid; i < NNZ; i += PREP_HALF) {
            int r = __ldg(row + i);
            int c = __ldg(col + i);
            int slot = atomicAdd(&cnt[r], 1);
            if (slot < CAP) {
                g_bucket[r * CAP + slot] = c;
            } else {
                int p = atomicAdd(&g_meta[0], 1);
                g_ovf[p] = make_int2(r, c);
            }
        }
    }
}

// Phase 2: HALF-WARP per row. One fp16 row = 256 B = 16 lanes x uint4
// (LDG.128). A warp covers 2 rows -> per-row LDG/shfl count HALVED vs R9.
// Slots processed in predicated zero-filled batches of 4 with a depth-2
// HADD2 tree per batch (same numeric structure as R9, rel_err ~3.6e-4).
// Slots 8-15 only when any half needs them; n>16 scans the overflow list.
__global__ __launch_bounds__(256) void gather_sum_kernel(
    float4* __restrict__ out) {
    const int gw   = (blockIdx.x * blockDim.x + threadIdx.x) >> 5;
    const int lane = threadIdx.x & 31;
    const int half = lane >> 4;         // 0 or 1
    const int lh   = lane & 15;         // lane within half
    const int r    = gw * 2 + half;
    if (r >= NC) return;                // NC even: whole warp exits together

    const int*   cnt   = g_meta + 1;
    const uint4* rows4 = g_half;        // fp16 row = 16 uint4

    // One 64B bucket line + count per half-warp, independent chains.
    int cj = __ldg(g_bucket + r * CAP + lh);
    int nr = __ldg(cnt + r);
    int n  = nr > CAP ? CAP : nr;

    float acc[8] = {0.f, 0.f, 0.f, 0.f, 0.f, 0.f, 0.f, 0.f};

    uint4 v[4];
    #pragma unroll
    for (int b = 0; b < 2; ++b) {       // slots 0-3, 4-7 (always)
        #pragma unroll
        for (int j = 0; j < 4; ++j) {
            int s = b * 4 + j;
            int c = __shfl_sync(0xffffffffu, cj, half * 16 + s);
            uint4 t = make_uint4(0u, 0u, 0u, 0u);
            if (s < n) t = __ldg(rows4 + (size_t)c * 16 + lh);
            v[j] = t;
        }
        #pragma unroll
        for (int k = 0; k < 4; ++k) {
            unsigned* c0 = &v[0].x; unsigned* c1 = &v[1].x;
            unsigned* c2 = &v[2].x; unsigned* c3 = &v[3].x;
            __half2 s0 = __hadd2(u2h(c0[k]), u2h(c1[k]));
            __half2 s1 = __hadd2(u2h(c2[k]), u2h(c3[k]));
            float2 f = __half22float2(__hadd2(s0, s1));
            acc[2*k]   += f.x;
            acc[2*k+1] += f.y;
        }
    }

    if (__any_sync(0xffffffffu, n > 8)) {
        #pragma unroll
        for (int b = 2; b < 4; ++b) {   // slots 8-11, 12-15
            #pragma unroll
            for (int j = 0; j < 4; ++j) {
                int s = b * 4 + j;
                int c = __shfl_sync(0xffffffffu, cj, half * 16 + s);
                uint4 t = make_uint4(0u, 0u, 0u, 0u);
                if (s < n) t = __ldg(rows4 + (size_t)c * 16 + lh);
                v[j] = t;
            }
            #pragma unroll
            for (int k = 0; k < 4; ++k) {
                unsigned* c0 = &v[0].x; unsigned* c1 = &v[1].x;
                unsigned* c2 = &v[2].x; unsigned* c3 = &v[3].x;
                __half2 s0 = __hadd2(u2h(c0[k]), u2h(c1[k]));
                __half2 s1 = __hadd2(u2h(c2[k]), u2h(c3[k]));
                float2 f = __half22float2(__hadd2(s0, s1));
                acc[2*k]   += f.x;
                acc[2*k+1] += f.y;
            }
        }
    }

    // Overflow rows (raw count > CAP, ~30 of 100k): scan the short list.
    if (__any_sync(0xffffffffu, nr > CAP)) {
        int ovfn = __ldg(&g_meta[0]);
        for (int i = 0; i < ovfn; ++i) {
            int2 e = __ldg(g_ovf + i);
            if (e.x == r) {
                uint4 h = __ldg(rows4 + (size_t)e.y * 16 + lh);
                float2 f0 = __half22float2(u2h(h.x));
                float2 f1 = __half22float2(u2h(h.y));
                float2 f2 = __half22float2(u2h(h.z));
                float2 f3 = __half22float2(u2h(h.w));
                acc[0] += f0.x; acc[1] += f0.y;
                acc[2] += f1.x; acc[3] += f1.y;
                acc[4] += f2.x; acc[5] += f2.y;
                acc[6] += f3.x; acc[7] += f3.y;
            }
        }
    }

    // Lane lh owns floats [8*lh, 8*lh+8) of row r = float4 slots 2lh, 2lh+1.
    size_t base = (size_t)r * 32 + lh * 2;
    out[base]     = make_float4(acc[0], acc[1], acc[2], acc[3]);
    out[base + 1] = make_float4(acc[4], acc[5], acc[6], acc[7]);
}

extern "C" void kernel_launch(void* const* d_in, const int* in_sizes, int n_in,
                              void* d_out, int out_size) {
    const float4* mat = (const float4*)d_in[0];
    const int*    row = (const int*)d_in[1];
    const int*    col = (const int*)d_in[2];
    float4*       out = (float4*)d_out;

    void* meta_ptr = nullptr;
    cudaGetSymbolAddress(&meta_ptr, g_meta);
    cudaMemsetAsync(meta_ptr, 0, (size_t)(NC + 1) * sizeof(int));

    prep_kernel<<<PREP_PAIRS * 2, PREP_T>>>(row, col, mat);

    // 50000 warps (2 rows each) = 1.6M threads / 256 = 6250 blocks.
    gather_sum_kernel<<<6250, 256>>>(out);
}